// round 6
// baseline (speedup 1.0000x reference)
#include <cuda_runtime.h>
#include <cuda_fp16.h>
#include <math.h>

#define NN 50000          // nodes
#define NE 400000         // edges (without self loops)
#define ET (NN + NE)      // total edges incl. self loops
#define NH 8              // heads
#define HC 512            // heads * channels
#define FIN 11            // input features

// ---------------- scratch (static device globals; no allocation) -------------
__device__ __align__(16) __half g_hh[(size_t)NN * HC];  // layer-1 features (51 MB, fp16)
__device__ __align__(16) float g_asrc[NN * NH];
__device__ __align__(16) float g_adst[NN * NH];
__device__ int   g_cnt[NN];
__device__ int   g_off[NN];
__device__ int   g_qend[NN];
__device__ int   g_cur[NN];
__device__ int   g_total;
__device__ int   g_ssrc[ET];
__device__ __align__(16) float g_w[(size_t)ET * NH];    // exp(edge score) (14.4 MB)
__device__ float g_h2[NN];
__device__ float g_a2s[NN];
__device__ float g_a2d[NN];
__device__ int   g_is64;

__device__ __forceinline__ float lrelu(float v) { return v > 0.f ? v : 0.2f * v; }
__device__ __forceinline__ float4 f4fma(float a, float4 v, float4 acc) {
    acc.x = fmaf(a, v.x, acc.x); acc.y = fmaf(a, v.y, acc.y);
    acc.z = fmaf(a, v.z, acc.z); acc.w = fmaf(a, v.w, acc.w); return acc;
}
__device__ __forceinline__ float f4dot(float4 a, float4 b) {
    return a.x * b.x + a.y * b.y + a.z * b.z + a.w * b.w;
}
__device__ __forceinline__ int edge_at(const void* ei, int idx, int is64) {
    return is64 ? (int)((const long long*)ei)[idx] : ((const int*)ei)[idx];
}
// fused-multiply-add 8 fp16 values (one uint4) into 8 fp32 accumulators
__device__ __forceinline__ void fma8(float w, uint4 v, float* acc) {
    const __half2* h = (const __half2*)&v;
#pragma unroll
    for (int k = 0; k < 4; k++) {
        float2 f = __half22float2(h[k]);
        acc[2 * k]     = fmaf(w, f.x, acc[2 * k]);
        acc[2 * k + 1] = fmaf(w, f.y, acc[2 * k + 1]);
    }
}

// ---------------- K0: zero histogram + dtype detect --------------------------
__global__ void k_zero(const void* ei, int n) {
    int i = blockIdx.x * blockDim.x + threadIdx.x;
    if (i < n) g_cnt[i] = 0;
    if (i == 0) {
        g_total = 0;
        const long long* p = (const long long*)ei;
        int ok = 1;
#pragma unroll 1
        for (int k = 0; k < 64; k++) {
            long long v = p[k];
            if (v < 0 || v >= n) { ok = 0; break; }
        }
        g_is64 = ok;
    }
}

// ---------------- K1: h = x@W1 (fp16 out), a_src, a_dst ----------------------
__global__ void k1(const float* __restrict__ x, const float* __restrict__ W1,
                   const float* __restrict__ as1, const float* __restrict__ ad1,
                   int nNodes) {
    __shared__ float sx[8][FIN];
    int t = threadIdx.x;
    int nb = blockIdx.x * 8;
    if (t < 8 * FIN) {
        int ni = t / FIN, k = t % FIN;
        int n = nb + ni;
        sx[ni][k] = (n < nNodes) ? x[(size_t)n * FIN + k] : 0.f;
    }
    float4 w[FIN];
#pragma unroll
    for (int k = 0; k < FIN; k++) w[k] = ((const float4*)W1)[k * 128 + t];
    float4 a4 = ((const float4*)as1)[t];
    float4 d4 = ((const float4*)ad1)[t];
    __syncthreads();
    int head = t >> 4;  // 16 threads per head
#pragma unroll 1
    for (int ni = 0; ni < 8; ni++) {
        int n = nb + ni;
        if (n >= nNodes) break;
        float4 acc = {0.f, 0.f, 0.f, 0.f};
#pragma unroll
        for (int k = 0; k < FIN; k++) acc = f4fma(sx[ni][k], w[k], acc);
        union { __half2 h2[2]; uint2 u; } pk;
        pk.h2[0] = __floats2half2_rn(acc.x, acc.y);
        pk.h2[1] = __floats2half2_rn(acc.z, acc.w);
        ((uint2*)g_hh)[(size_t)n * 128 + t] = pk.u;
        float ps = f4dot(acc, a4);
        float pd = f4dot(acc, d4);
#pragma unroll
        for (int o = 8; o >= 1; o >>= 1) {
            ps += __shfl_xor_sync(0xffffffffu, ps, o);
            pd += __shfl_xor_sync(0xffffffffu, pd, o);
        }
        if ((t & 15) == 0) {
            g_asrc[n * NH + head] = ps;
            g_adst[n * NH + head] = pd;
        }
    }
}

// ---------------- K2: histogram of dst degrees -------------------------------
__global__ void k_hist(const void* __restrict__ ei, int nE, int nNodes) {
    int i = blockIdx.x * blockDim.x + threadIdx.x;
    int tot = nE + nNodes;
    if (i >= tot) return;
    int d = (i < nE) ? edge_at(ei, nE + i, g_is64) : (i - nE);
    if ((unsigned)d >= (unsigned)nNodes) return;
    atomicAdd(&g_cnt[d], 1);
}

// ---------------- K3: offsets via warp-aggregated atomic bump ----------------
__global__ void k_offsets(int nNodes) {
    int n = blockIdx.x * blockDim.x + threadIdx.x;
    int lane = threadIdx.x & 31;
    int c = (n < nNodes) ? g_cnt[n] : 0;
    int incl = c;
#pragma unroll
    for (int o = 1; o < 32; o <<= 1) {
        int v = __shfl_up_sync(0xffffffffu, incl, o);
        if (lane >= o) incl += v;
    }
    int wtot = __shfl_sync(0xffffffffu, incl, 31);
    int base = 0;
    if (lane == 31) base = atomicAdd(&g_total, wtot);
    base = __shfl_sync(0xffffffffu, base, 31);
    if (n < nNodes) {
        int start = base + incl - c;
        g_off[n]  = start;
        g_qend[n] = start + c;
        g_cur[n]  = start;
    }
}

// ---------------- K4: scatter sorted edges + exp(edge scores) ----------------
__global__ void k_scatter(const void* __restrict__ ei, int nE, int nNodes) {
    int i = blockIdx.x * blockDim.x + threadIdx.x;
    int tot = nE + nNodes;
    if (i >= tot) return;
    int is64 = g_is64;
    int s, d;
    if (i < nE) { s = edge_at(ei, i, is64); d = edge_at(ei, nE + i, is64); }
    else        { s = d = i - nE; }
    if ((unsigned)d >= (unsigned)nNodes || (unsigned)s >= (unsigned)nNodes) return;
    int pos = atomicAdd(&g_cur[d], 1);
    g_ssrc[pos] = s;
    float4 a0 = ((const float4*)&g_asrc[s * NH])[0];
    float4 a1 = ((const float4*)&g_asrc[s * NH])[1];
    float4 d0 = ((const float4*)&g_adst[d * NH])[0];
    float4 d1 = ((const float4*)&g_adst[d * NH])[1];
    float4 e0, e1;
    e0.x = __expf(lrelu(a0.x + d0.x)); e0.y = __expf(lrelu(a0.y + d0.y));
    e0.z = __expf(lrelu(a0.z + d0.z)); e0.w = __expf(lrelu(a0.w + d0.w));
    e1.x = __expf(lrelu(a1.x + d1.x)); e1.y = __expf(lrelu(a1.y + d1.y));
    e1.z = __expf(lrelu(a1.z + d1.z)); e1.w = __expf(lrelu(a1.w + d1.w));
    ((float4*)&g_w[(size_t)pos * NH])[0] = e0;
    ((float4*)&g_w[(size_t)pos * NH])[1] = e1;
}

// ---------------- K5: aggregation, 2 warps per node --------------------------
// Block = 256 thr = 8 warps = 4 nodes. Warp parity P owns heads 4P..4P+3,
// channels [256P, 256P+256). Lane owns 8 contiguous channels 256P+8*lane,
// head = 4P + (lane>>3). Halves per-thread registers & serial edge chain,
// doubles resident warps vs. 1-warp-per-node.
__global__ void k_agg(const float* __restrict__ b1, const float* __restrict__ W2,
                      const float* __restrict__ as2, const float* __restrict__ ad2,
                      int nNodes) {
    __shared__ float sdot[8];
    int wid  = threadIdx.x >> 5;
    int lane = threadIdx.x & 31;
    int P    = wid & 1;
    int n    = blockIdx.x * 4 + (wid >> 1);
    bool act = (n < nNodes);
    int p = 0, q = 0;
    if (act) { p = g_off[n]; q = g_qend[n]; }

    // pass 1: sums of exp weights for this warp's 4 heads
    float s0 = 0.f, s1 = 0.f, s2 = 0.f, s3 = 0.f;
    for (int i = p + lane; i < q; i += 32) {
        float4 e = *(const float4*)&g_w[(size_t)i * NH + 4 * P];
        s0 += e.x; s1 += e.y; s2 += e.z; s3 += e.w;
    }
#pragma unroll
    for (int o = 16; o; o >>= 1) {
        s0 += __shfl_xor_sync(0xffffffffu, s0, o);
        s1 += __shfl_xor_sync(0xffffffffu, s1, o);
        s2 += __shfl_xor_sync(0xffffffffu, s2, o);
        s3 += __shfl_xor_sync(0xffffffffu, s3, o);
    }
    int hsel = lane >> 3;                  // 0..3 within this warp's heads
    float sh = (hsel == 0) ? s0 : (hsel == 1) ? s1 : (hsel == 2) ? s2 : s3;
    float inv = 1.f / (sh + 1e-16f);

    // pass 2: weighted gather (unroll x2; 2 uint4 in flight per lane)
    float acc[8];
#pragma unroll
    for (int k = 0; k < 8; k++) acc[k] = 0.f;
    int i = p;
#pragma unroll 1
    for (; i + 2 <= q; i += 2) {
        int sn0 = g_ssrc[i];
        int sn1 = g_ssrc[i + 1];
        float w0 = g_w[(size_t)i * NH + 4 * P + hsel];
        float w1 = g_w[(size_t)(i + 1) * NH + 4 * P + hsel];
        uint4 v0 = ((const uint4*)&g_hh[(size_t)sn0 * HC])[32 * P + lane];
        uint4 v1 = ((const uint4*)&g_hh[(size_t)sn1 * HC])[32 * P + lane];
        fma8(w0 * inv, v0, acc);
        fma8(w1 * inv, v1, acc);
    }
    if (i < q) {
        int sn = g_ssrc[i];
        float w = g_w[(size_t)i * NH + 4 * P + hsel];
        uint4 v = ((const uint4*)&g_hh[(size_t)sn * HC])[32 * P + lane];
        fma8(w * inv, v, acc);
    }

    // epilogue: + b1, ELU, partial dot with W2 over this warp's 256 channels
    float dot = 0.f;
    int ch = 256 * P + 8 * lane;
#pragma unroll
    for (int k = 0; k < 8; k++) {
        float v = acc[k] + b1[ch + k];
        v = v > 0.f ? v : __expf(v) - 1.f;
        dot = fmaf(v, W2[ch + k], dot);
    }
#pragma unroll
    for (int o = 16; o; o >>= 1) dot += __shfl_xor_sync(0xffffffffu, dot, o);
    if (lane == 0) sdot[wid] = dot;
    __syncthreads();
    if (act && P == 0 && lane == 0) {
        float d2 = sdot[wid] + sdot[wid + 1];
        g_h2[n]  = d2;
        g_a2s[n] = d2 * as2[0];
        g_a2d[n] = d2 * ad2[0];
    }
}

// ---------------- K6: layer-2 attention (warp per node, single pass) ---------
__global__ void k_l2(float* __restrict__ out, const float* __restrict__ b2, int nNodes) {
    int n = (blockIdx.x * blockDim.x + threadIdx.x) >> 5;
    int lane = threadIdx.x & 31;
    if (n >= nNodes) return;
    int p = g_off[n], q = g_qend[n];
    float ad = g_a2d[n];
    float sum = 0.f, acc = 0.f;
    for (int i = p + lane; i < q; i += 32) {
        int sn = g_ssrc[i];
        float v = __expf(lrelu(g_a2s[sn] + ad));
        sum += v;
        acc = fmaf(v, g_h2[sn], acc);
    }
#pragma unroll
    for (int o = 16; o; o >>= 1) {
        sum += __shfl_xor_sync(0xffffffffu, sum, o);
        acc += __shfl_xor_sync(0xffffffffu, acc, o);
    }
    if (lane == 0) out[n] = acc / (sum + 1e-16f) + b2[0];
}

// ---------------- launch -----------------------------------------------------
extern "C" void kernel_launch(void* const* d_in, const int* in_sizes, int n_in,
                              void* d_out, int out_size) {
    const float* x   = (const float*)d_in[0];
    const void*  ei  = d_in[1];
    const float* W1  = (const float*)d_in[2];
    const float* as1 = (const float*)d_in[3];
    const float* ad1 = (const float*)d_in[4];
    const float* b1  = (const float*)d_in[5];
    const float* W2  = (const float*)d_in[6];
    const float* as2 = (const float*)d_in[7];
    const float* ad2 = (const float*)d_in[8];
    const float* b2  = (const float*)d_in[9];

    int nN = in_sizes[0] / FIN;   // 50000
    int nE = in_sizes[1] / 2;     // 400000
    int tot = nN + nE;

    k_zero   <<<(nN + 255) / 256, 256>>>(ei, nN);
    k1       <<<(nN + 7) / 8, 128>>>(x, W1, as1, ad1, nN);
    k_hist   <<<(tot + 255) / 256, 256>>>(ei, nE, nN);
    k_offsets<<<(nN + 255) / 256, 256>>>(nN);
    k_scatter<<<(tot + 255) / 256, 256>>>(ei, nE, nN);
    k_agg    <<<(nN + 3) / 4, 256>>>(b1, W2, as2, ad2, nN);
    k_l2     <<<(nN + 7) / 8, 256>>>((float*)d_out, b2, nN);
}

// round 7
// speedup vs baseline: 1.0380x; 1.0380x over previous
#include <cuda_runtime.h>
#include <cuda_fp16.h>
#include <math.h>

#define NN 50000          // nodes
#define NE 400000         // edges (without self loops)
#define ET (NN + NE)      // total edges incl. self loops
#define NH 8              // heads
#define HC 512            // heads * channels
#define FIN 11            // input features
#define K1B ((NN + 7) / 8)                 // k1 blocks inside merged kernel
#define HISTB ((ET + 127) / 128)           // hist blocks inside merged kernel
#define PD 4                               // cp.async pipeline depth

// ---------------- scratch (static device globals; no allocation) -------------
__device__ __align__(16) __half g_hh[(size_t)NN * HC];  // layer-1 features (51 MB, fp16)
__device__ __align__(16) float g_asrc[NN * NH];
__device__ __align__(16) float g_adst[NN * NH];
__device__ int   g_cnt[NN];
__device__ int   g_off[NN];
__device__ int   g_qend[NN];
__device__ int   g_cur[NN];
__device__ int   g_total;
__device__ int   g_ssrc[ET];
__device__ __align__(16) float g_w[(size_t)ET * NH];    // exp(edge score) (14.4 MB)
__device__ float g_h2[NN];
__device__ float g_a2s[NN];
__device__ float g_a2d[NN];
__device__ int   g_is64;

__device__ __forceinline__ float lrelu(float v) { return v > 0.f ? v : 0.2f * v; }
__device__ __forceinline__ float4 f4fma(float a, float4 v, float4 acc) {
    acc.x = fmaf(a, v.x, acc.x); acc.y = fmaf(a, v.y, acc.y);
    acc.z = fmaf(a, v.z, acc.z); acc.w = fmaf(a, v.w, acc.w); return acc;
}
__device__ __forceinline__ float f4dot(float4 a, float4 b) {
    return a.x * b.x + a.y * b.y + a.z * b.z + a.w * b.w;
}
__device__ __forceinline__ int edge_at(const void* ei, int idx, int is64) {
    return is64 ? (int)((const long long*)ei)[idx] : ((const int*)ei)[idx];
}
__device__ __forceinline__ void fma8(float w, uint4 v, float* acc) {
    const __half2* h = (const __half2*)&v;
#pragma unroll
    for (int k = 0; k < 4; k++) {
        float2 f = __half22float2(h[k]);
        acc[2 * k]     = fmaf(w, f.x, acc[2 * k]);
        acc[2 * k + 1] = fmaf(w, f.y, acc[2 * k + 1]);
    }
}
__device__ __forceinline__ void cpa16(void* smem_dst, const void* gmem_src) {
    unsigned d = (unsigned)__cvta_generic_to_shared(smem_dst);
    asm volatile("cp.async.cg.shared.global [%0], [%1], 16;\n" :: "r"(d), "l"(gmem_src));
}
#define CPA_COMMIT()  asm volatile("cp.async.commit_group;\n" ::: "memory")
#define CPA_WAIT(n)   asm volatile("cp.async.wait_group %0;\n" :: "n"(n) : "memory")

// ---------------- K0: zero histogram + dtype detect --------------------------
__global__ void k_zero(const void* ei, int n) {
    int i = blockIdx.x * blockDim.x + threadIdx.x;
    if (i < n) g_cnt[i] = 0;
    if (i == 0) {
        g_total = 0;
        const long long* p = (const long long*)ei;
        int ok = 1;
#pragma unroll 1
        for (int k = 0; k < 64; k++) {
            long long v = p[k];
            if (v < 0 || v >= n) { ok = 0; break; }
        }
        g_is64 = ok;
    }
}

// ---------------- K1+K2 merged: feature transform | degree histogram ---------
// Blocks [0, K1B): k1 role (8 nodes/block, 128 thr).
// Blocks [K1B, K1B+HISTB): histogram role (128 edges/block).
__global__ void k1_hist(const float* __restrict__ x, const float* __restrict__ W1,
                        const float* __restrict__ as1, const float* __restrict__ ad1,
                        const void* __restrict__ ei, int nNodes, int nE) {
    int t = threadIdx.x;
    if (blockIdx.x >= K1B) {                 // ---- histogram role ----
        int i = (blockIdx.x - K1B) * 128 + t;
        int tot = nE + nNodes;
        if (i >= tot) return;
        int d = (i < nE) ? edge_at(ei, nE + i, g_is64) : (i - nE);
        if ((unsigned)d >= (unsigned)nNodes) return;
        atomicAdd(&g_cnt[d], 1);
        return;
    }
    // ---- k1 role ----
    __shared__ float sx[8][FIN];
    int nb = blockIdx.x * 8;
    if (t < 8 * FIN) {
        int ni = t / FIN, k = t % FIN;
        int n = nb + ni;
        sx[ni][k] = (n < nNodes) ? x[(size_t)n * FIN + k] : 0.f;
    }
    float4 w[FIN];
#pragma unroll
    for (int k = 0; k < FIN; k++) w[k] = ((const float4*)W1)[k * 128 + t];
    float4 a4 = ((const float4*)as1)[t];
    float4 d4 = ((const float4*)ad1)[t];
    __syncthreads();
    int head = t >> 4;  // 16 threads per head
#pragma unroll 1
    for (int ni = 0; ni < 8; ni++) {
        int n = nb + ni;
        if (n >= nNodes) break;
        float4 acc = {0.f, 0.f, 0.f, 0.f};
#pragma unroll
        for (int k = 0; k < FIN; k++) acc = f4fma(sx[ni][k], w[k], acc);
        union { __half2 h2[2]; uint2 u; } pk;
        pk.h2[0] = __floats2half2_rn(acc.x, acc.y);
        pk.h2[1] = __floats2half2_rn(acc.z, acc.w);
        ((uint2*)g_hh)[(size_t)n * 128 + t] = pk.u;
        float ps = f4dot(acc, a4);
        float pd = f4dot(acc, d4);
#pragma unroll
        for (int o = 8; o >= 1; o >>= 1) {
            ps += __shfl_xor_sync(0xffffffffu, ps, o);
            pd += __shfl_xor_sync(0xffffffffu, pd, o);
        }
        if ((t & 15) == 0) {
            g_asrc[n * NH + head] = ps;
            g_adst[n * NH + head] = pd;
        }
    }
}

// ---------------- K3: offsets via warp-aggregated atomic bump ----------------
__global__ void k_offsets(int nNodes) {
    int n = blockIdx.x * blockDim.x + threadIdx.x;
    int lane = threadIdx.x & 31;
    int c = (n < nNodes) ? g_cnt[n] : 0;
    int incl = c;
#pragma unroll
    for (int o = 1; o < 32; o <<= 1) {
        int v = __shfl_up_sync(0xffffffffu, incl, o);
        if (lane >= o) incl += v;
    }
    int wtot = __shfl_sync(0xffffffffu, incl, 31);
    int base = 0;
    if (lane == 31) base = atomicAdd(&g_total, wtot);
    base = __shfl_sync(0xffffffffu, base, 31);
    if (n < nNodes) {
        int start = base + incl - c;
        g_off[n]  = start;
        g_qend[n] = start + c;
        g_cur[n]  = start;
    }
}

// ---------------- K4: scatter sorted edges + exp(edge scores) ----------------
__global__ void k_scatter(const void* __restrict__ ei, int nE, int nNodes) {
    int i = blockIdx.x * blockDim.x + threadIdx.x;
    int tot = nE + nNodes;
    if (i >= tot) return;
    int is64 = g_is64;
    int s, d;
    if (i < nE) { s = edge_at(ei, i, is64); d = edge_at(ei, nE + i, is64); }
    else        { s = d = i - nE; }
    if ((unsigned)d >= (unsigned)nNodes || (unsigned)s >= (unsigned)nNodes) return;
    int pos = atomicAdd(&g_cur[d], 1);
    g_ssrc[pos] = s;
    float4 a0 = ((const float4*)&g_asrc[s * NH])[0];
    float4 a1 = ((const float4*)&g_asrc[s * NH])[1];
    float4 d0 = ((const float4*)&g_adst[d * NH])[0];
    float4 d1 = ((const float4*)&g_adst[d * NH])[1];
    float4 e0, e1;
    e0.x = __expf(lrelu(a0.x + d0.x)); e0.y = __expf(lrelu(a0.y + d0.y));
    e0.z = __expf(lrelu(a0.z + d0.z)); e0.w = __expf(lrelu(a0.w + d0.w));
    e1.x = __expf(lrelu(a1.x + d1.x)); e1.y = __expf(lrelu(a1.y + d1.y));
    e1.z = __expf(lrelu(a1.z + d1.z)); e1.w = __expf(lrelu(a1.w + d1.w));
    ((float4*)&g_w[(size_t)pos * NH])[0] = e0;
    ((float4*)&g_w[(size_t)pos * NH])[1] = e1;
}

// ---------------- K5: aggregation (1 warp/node, cp.async depth-4 pipeline) ---
// Lane L owns channels [8L,8L+8) (head L>>3) and [256+8L,+8) (head (L>>3)+4).
// Per edge each lane issues 2x16B cp.async into a 4-stage smem ring; in-flight
// data lives in smem, so MLP=8x16B/lane without register pressure.
__global__ void k_agg(const float* __restrict__ b1, const float* __restrict__ W2,
                      const float* __restrict__ as2, const float* __restrict__ ad2,
                      int nNodes) {
    __shared__ __align__(16) uint4 stage[8][PD][64];   // 8 warps x 4 stages x 1KB
    int wid  = threadIdx.x >> 5;
    int lane = threadIdx.x & 31;
    int n = blockIdx.x * 8 + wid;
    if (n >= nNodes) return;
    int p = g_off[n], q = g_qend[n];

    // pass 1: per-head sum of exp weights (also warms g_w rows in L2)
    float s[NH];
#pragma unroll
    for (int h = 0; h < NH; h++) s[h] = 0.f;
    for (int i = p + lane; i < q; i += 32) {
        float4 e0 = ((const float4*)&g_w[(size_t)i * NH])[0];
        float4 e1 = ((const float4*)&g_w[(size_t)i * NH])[1];
        s[0] += e0.x; s[1] += e0.y; s[2] += e0.z; s[3] += e0.w;
        s[4] += e1.x; s[5] += e1.y; s[6] += e1.z; s[7] += e1.w;
    }
#pragma unroll
    for (int o = 16; o; o >>= 1)
#pragma unroll
        for (int h = 0; h < NH; h++)
            s[h] += __shfl_xor_sync(0xffffffffu, s[h], o);

    int hA = lane >> 3;                       // 0..3
    float iA = 1.f / (s[hA]     + 1e-16f);
    float iB = 1.f / (s[hA + 4] + 1e-16f);

    // pass 2: cp.async-pipelined weighted gather
    float accA[8], accB[8];
#pragma unroll
    for (int k = 0; k < 8; k++) { accA[k] = 0.f; accB[k] = 0.f; }

    // prologue: issue first PD edges
#pragma unroll
    for (int st = 0; st < PD; st++) {
        int j = p + st;
        if (j < q) {
            int sn = g_ssrc[j];
            const uint4* hr = (const uint4*)&g_hh[(size_t)sn * HC];
            cpa16(&stage[wid][st][lane],      hr + lane);
            cpa16(&stage[wid][st][lane + 32], hr + lane + 32);
        }
        CPA_COMMIT();
    }
    float wA = 0.f, wB = 0.f;
    if (p < q) {
        wA = g_w[(size_t)p * NH + hA];
        wB = g_w[(size_t)p * NH + hA + 4];
    }
#pragma unroll 1
    for (int i = p; i < q; i++) {
        int st = (i - p) & (PD - 1);
        CPA_WAIT(PD - 1);                     // oldest group (this stage) done
        uint4 vA = stage[wid][st][lane];
        uint4 vB = stage[wid][st][lane + 32];
        float cwA = wA, cwB = wB;
        if (i + 1 < q) {                      // prefetch next edge's weights
            wA = g_w[(size_t)(i + 1) * NH + hA];
            wB = g_w[(size_t)(i + 1) * NH + hA + 4];
        }
        int j = i + PD;                       // refill this stage
        if (j < q) {
            int sn = g_ssrc[j];
            const uint4* hr = (const uint4*)&g_hh[(size_t)sn * HC];
            cpa16(&stage[wid][st][lane],      hr + lane);
            cpa16(&stage[wid][st][lane + 32], hr + lane + 32);
        }
        CPA_COMMIT();
        fma8(cwA * iA, vA, accA);
        fma8(cwB * iB, vB, accB);
    }

    // epilogue: + b1, ELU, project with W2, warp-reduce -> h2 scalar
    float dot = 0.f;
#pragma unroll
    for (int k = 0; k < 8; k++) {
        float vA = accA[k] + b1[8 * lane + k];
        vA = vA > 0.f ? vA : __expf(vA) - 1.f;
        dot = fmaf(vA, W2[8 * lane + k], dot);
        float vB = accB[k] + b1[256 + 8 * lane + k];
        vB = vB > 0.f ? vB : __expf(vB) - 1.f;
        dot = fmaf(vB, W2[256 + 8 * lane + k], dot);
    }
#pragma unroll
    for (int o = 16; o; o >>= 1) dot += __shfl_xor_sync(0xffffffffu, dot, o);
    if (lane == 0) {
        g_h2[n]  = dot;
        g_a2s[n] = dot * as2[0];
        g_a2d[n] = dot * ad2[0];
    }
}

// ---------------- K6: layer-2 attention (warp per node, single pass) ---------
__global__ void k_l2(float* __restrict__ out, const float* __restrict__ b2, int nNodes) {
    int n = (blockIdx.x * blockDim.x + threadIdx.x) >> 5;
    int lane = threadIdx.x & 31;
    if (n >= nNodes) return;
    int p = g_off[n], q = g_qend[n];
    float ad = g_a2d[n];
    float sum = 0.f, acc = 0.f;
    for (int i = p + lane; i < q; i += 32) {
        int sn = g_ssrc[i];
        float v = __expf(lrelu(g_a2s[sn] + ad));
        sum += v;
        acc = fmaf(v, g_h2[sn], acc);
    }
#pragma unroll
    for (int o = 16; o; o >>= 1) {
        sum += __shfl_xor_sync(0xffffffffu, sum, o);
        acc += __shfl_xor_sync(0xffffffffu, acc, o);
    }
    if (lane == 0) out[n] = acc / (sum + 1e-16f) + b2[0];
}

// ---------------- launch -----------------------------------------------------
extern "C" void kernel_launch(void* const* d_in, const int* in_sizes, int n_in,
                              void* d_out, int out_size) {
    const float* x   = (const float*)d_in[0];
    const void*  ei  = d_in[1];
    const float* W1  = (const float*)d_in[2];
    const float* as1 = (const float*)d_in[3];
    const float* ad1 = (const float*)d_in[4];
    const float* b1  = (const float*)d_in[5];
    const float* W2  = (const float*)d_in[6];
    const float* as2 = (const float*)d_in[7];
    const float* ad2 = (const float*)d_in[8];
    const float* b2  = (const float*)d_in[9];

    int nN = in_sizes[0] / FIN;   // 50000
    int nE = in_sizes[1] / 2;     // 400000
    int tot = nN + nE;

    k_zero   <<<(nN + 255) / 256, 256>>>(ei, nN);
    k1_hist  <<<K1B + HISTB, 128>>>(x, W1, as1, ad1, ei, nN, nE);
    k_offsets<<<(nN + 255) / 256, 256>>>(nN);
    k_scatter<<<(tot + 255) / 256, 256>>>(ei, nE, nN);
    k_agg    <<<(nN + 7) / 8, 256>>>(b1, W2, as2, ad2, nN);
    k_l2     <<<(nN + 7) / 8, 256>>>((float*)d_out, b2, nN);
}